// round 1
// baseline (speedup 1.0000x reference)
#include <cuda_runtime.h>
#include <cuda_bf16.h>
#include <math.h>

// Problem constants (fixed shapes from reference)
#define CC   192
#define NN   4096           // D*H*W = 16^3
#define HID  384            // 2*C
#define MLPH 768            // 4*C
#define NH   6
#define HD   32
#define K3   125
#define QKV3 576            // 3*C

// ---------------- scratch (device globals; no allocation allowed) ----------
__device__ float g_sum[CC];
__device__ float g_sumsq[CC];
__device__ float g_h[HID];
__device__ float g_mult[CC];
__device__ float g_qkv[(size_t)NN * QKV3];
__device__ float g_oatt[(size_t)NN * CC];
__device__ float g_x2[(size_t)CC * NN];
__device__ float g_m1[(size_t)MLPH * NN];

// ---------------- helpers ---------------------------------------------------
__device__ __forceinline__ float warp_sum(float v) {
#pragma unroll
    for (int o = 16; o; o >>= 1) v += __shfl_xor_sync(0xffffffffu, v, o);
    return v;
}
__device__ __forceinline__ float warp_max(float v) {
#pragma unroll
    for (int o = 16; o; o >>= 1) v = fmaxf(v, __shfl_xor_sync(0xffffffffu, v, o));
    return v;
}

// ---------------- per-channel sum / sumsq ----------------------------------
__global__ void chan_stats_kernel(const float* __restrict__ x,
                                  float* __restrict__ sums,
                                  float* __restrict__ sumsq) {
    __shared__ float ss[8], ss2[8];
    int c = blockIdx.x;
    const float* p = x + (size_t)c * NN;
    float s = 0.f, s2 = 0.f;
    for (int i = threadIdx.x; i < NN; i += 256) {
        float v = p[i];
        s += v; s2 += v * v;
    }
    s = warp_sum(s); s2 = warp_sum(s2);
    int wid = threadIdx.x >> 5, lane = threadIdx.x & 31;
    if (lane == 0) { ss[wid] = s; ss2[wid] = s2; }
    __syncthreads();
    if (threadIdx.x == 0) {
        float a = 0.f, b = 0.f;
#pragma unroll
        for (int i = 0; i < 8; i++) { a += ss[i]; b += ss2[i]; }
        sums[c] = a; sumsq[c] = b;
    }
}

// ---------------- ada gating MLP: h = relu(mean @ w1^T + b1) ---------------
__global__ void ada_hidden_kernel(const float* __restrict__ sums,
                                  const float* __restrict__ w1,
                                  const float* __restrict__ b1,
                                  float* __restrict__ hout) {
    int gw = (blockIdx.x * blockDim.x + threadIdx.x) >> 5;
    int lane = threadIdx.x & 31;
    if (gw >= HID) return;
    const float* wr = w1 + (size_t)gw * CC;
    float acc = 0.f;
    for (int c = lane; c < CC; c += 32)
        acc += (sums[c] * (1.f / NN)) * wr[c];
    acc = warp_sum(acc);
    if (lane == 0) hout[gw] = fmaxf(acc + b1[gw], 0.f);
}

// mult[c] = scale[c] * sigmoid(h @ w2[c] + b2[c]) / sqrt(mean(x^2)+eps)
__global__ void ada_mult_kernel(const float* __restrict__ hvec,
                                const float* __restrict__ w2,
                                const float* __restrict__ b2,
                                const float* __restrict__ scale,
                                const float* __restrict__ sumsq,
                                float* __restrict__ mult) {
    int gw = (blockIdx.x * blockDim.x + threadIdx.x) >> 5;
    int lane = threadIdx.x & 31;
    if (gw >= CC) return;
    const float* wr = w2 + (size_t)gw * HID;
    float acc = 0.f;
    for (int i = lane; i < HID; i += 32) acc += hvec[i] * wr[i];
    acc = warp_sum(acc);
    if (lane == 0) {
        float g = 1.f / (1.f + __expf(-(acc + b2[gw])));
        mult[gw] = scale[gw] * g * rsqrtf(sumsq[gw] * (1.f / NN) + 1e-6f);
    }
}

// ---------------- generic 64x64x16 tiled GEMM -------------------------------
// out[i][j] = epilogue( sum_k opA(i,k) * opB(j,k) )
// mode 0: operand is row-major (rows, K), ld = K
// mode 1: operand is "x-like": src (K, rows) column access, ld = rows-stride,
//         each k scaled by mult[k] (mult may be null => 1.0)
#define TM 64
#define TN 64
#define TK 16

template <int AMODE, int BMODE>
__global__ void gemm_kernel(int M, int N, int K,
                            const float* __restrict__ A, int lda, const float* __restrict__ Amult,
                            const float* __restrict__ B, int ldb, const float* __restrict__ Bmult,
                            float* __restrict__ out, int ldo,
                            const float* __restrict__ bias, int bias_per_j,
                            const float* __restrict__ residual, int do_gelu) {
    __shared__ float As[TK][TM + 4];
    __shared__ float Bs[TK][TN + 4];
    const int i0 = blockIdx.y * TM;
    const int j0 = blockIdx.x * TN;
    const int tid = threadIdx.x;
    const int ty = tid >> 4, tx = tid & 15;

    float acc[4][4] = {};

    for (int k0 = 0; k0 < K; k0 += TK) {
        if (AMODE == 0) {
#pragma unroll
            for (int e = tid; e < TM * TK; e += 256) {
                int ii = e >> 4, kk = e & 15;
                As[kk][ii] = A[(size_t)(i0 + ii) * lda + (k0 + kk)];
            }
        } else {
#pragma unroll
            for (int e = tid; e < TM * TK; e += 256) {
                int ii = e & 63, kk = e >> 6;
                float m = Amult ? Amult[k0 + kk] : 1.f;
                As[kk][ii] = A[(size_t)(k0 + kk) * lda + (i0 + ii)] * m;
            }
        }
        if (BMODE == 0) {
#pragma unroll
            for (int e = tid; e < TN * TK; e += 256) {
                int jj = e >> 4, kk = e & 15;
                Bs[kk][jj] = B[(size_t)(j0 + jj) * ldb + (k0 + kk)];
            }
        } else {
#pragma unroll
            for (int e = tid; e < TN * TK; e += 256) {
                int jj = e & 63, kk = e >> 6;
                float m = Bmult ? Bmult[k0 + kk] : 1.f;
                Bs[kk][jj] = B[(size_t)(k0 + kk) * ldb + (j0 + jj)] * m;
            }
        }
        __syncthreads();
#pragma unroll
        for (int kk = 0; kk < TK; kk++) {
            float4 a4 = *(const float4*)&As[kk][ty * 4];
            float4 b4 = *(const float4*)&Bs[kk][tx * 4];
            float a[4] = {a4.x, a4.y, a4.z, a4.w};
            float b[4] = {b4.x, b4.y, b4.z, b4.w};
#pragma unroll
            for (int u = 0; u < 4; u++)
#pragma unroll
                for (int v = 0; v < 4; v++)
                    acc[u][v] = fmaf(a[u], b[v], acc[u][v]);
        }
        __syncthreads();
    }

#pragma unroll
    for (int u = 0; u < 4; u++) {
        int i = i0 + ty * 4 + u;
        int j = j0 + tx * 4;
        float vals[4];
#pragma unroll
        for (int v = 0; v < 4; v++) {
            float val = acc[u][v];
            if (bias) val += bias_per_j ? bias[j + v] : bias[i];
            if (do_gelu) val = 0.5f * val * (1.f + erff(val * 0.70710678118654752f));
            vals[v] = val;
        }
        if (residual) {
            float4 rr = *(const float4*)&residual[(size_t)i * ldo + j];
            vals[0] += rr.x; vals[1] += rr.y; vals[2] += rr.z; vals[3] += rr.w;
        }
        *(float4*)&out[(size_t)i * ldo + j] =
            make_float4(vals[0], vals[1], vals[2], vals[3]);
    }
}

// ---------------- neighborhood attention -----------------------------------
// One block per spatial position (n), one warp per head.
// qkv layout: (n, 576) with q[0:192), k[192:384), v[384:576), head*32+c.
__global__ void natt_kernel(const float* __restrict__ qkv,
                            float* __restrict__ oatt) {
    __shared__ int nbr[K3];
    __shared__ float sc[NH][128];

    const int n = blockIdx.x;
    const int d = n >> 8, h = (n >> 4) & 15, w = n & 15;
    const int tid = threadIdx.x;
    const int wid = tid >> 5, lane = tid & 31;

    if (tid < K3) {
        int a = tid / 25, b = (tid / 5) % 5, c = tid % 5;
        int sd = min(max(d - 2, 0), 11);
        int sh = min(max(h - 2, 0), 11);
        int sw = min(max(w - 2, 0), 11);
        nbr[tid] = (sd + a) * 256 + (sh + b) * 16 + (sw + c);
    }
    __syncthreads();

    const float scaleqk = 0.17677669529663687f; // 1/sqrt(32)
    const int hoff = wid * HD + lane;
    const float qv = qkv[(size_t)n * QKV3 + hoff];

    // pass 1: scores
    for (int j = 0; j < K3; j++) {
        float kv = qkv[(size_t)nbr[j] * QKV3 + CC + hoff];
        float s = warp_sum(qv * kv);
        if (lane == 0) sc[wid][j] = s * scaleqk;
    }
    __syncwarp();

    // softmax over 125 (lane handles lane, lane+32, lane+64, lane+96)
    float x0 = sc[wid][lane];
    float x1 = sc[wid][lane + 32];
    float x2 = sc[wid][lane + 64];
    float x3 = (lane < 29) ? sc[wid][lane + 96] : -1e30f;
    float m = warp_max(fmaxf(fmaxf(x0, x1), fmaxf(x2, x3)));
    float e0 = __expf(x0 - m);
    float e1 = __expf(x1 - m);
    float e2 = __expf(x2 - m);
    float e3 = (lane < 29) ? __expf(x3 - m) : 0.f;
    float ssum = warp_sum(e0 + e1 + e2 + e3);
    float inv = 1.f / ssum;
    sc[wid][lane] = e0;
    sc[wid][lane + 32] = e1;
    sc[wid][lane + 64] = e2;
    if (lane < 29) sc[wid][lane + 96] = e3;
    __syncwarp();

    // pass 2: o[c] = sum_j p[j] * v[nbr[j]][c]   (lane = channel)
    float acc = 0.f;
    for (int j = 0; j < K3; j++) {
        float vv = qkv[(size_t)nbr[j] * QKV3 + 2 * CC + hoff];
        acc = fmaf(sc[wid][j], vv, acc);
    }
    oatt[(size_t)n * CC + hoff] = acc * inv;
}

// ---------------- launch -----------------------------------------------------
extern "C" void kernel_launch(void* const* d_in, const int* in_sizes, int n_in,
                              void* d_out, int out_size) {
    const float* x      = (const float*)d_in[0];
    const float* scale1 = (const float*)d_in[1];
    const float* n1_w1  = (const float*)d_in[2];
    const float* n1_b1  = (const float*)d_in[3];
    const float* n1_w2  = (const float*)d_in[4];
    const float* n1_b2  = (const float*)d_in[5];
    const float* qkv_w  = (const float*)d_in[6];
    const float* qkv_b  = (const float*)d_in[7];
    const float* proj_w = (const float*)d_in[8];
    const float* proj_b = (const float*)d_in[9];
    const float* scale2 = (const float*)d_in[10];
    const float* n2_w1  = (const float*)d_in[11];
    const float* n2_b1  = (const float*)d_in[12];
    const float* n2_w2  = (const float*)d_in[13];
    const float* n2_b2  = (const float*)d_in[14];
    const float* mlp_w1 = (const float*)d_in[15];
    const float* mlp_b1 = (const float*)d_in[16];
    const float* mlp_w2 = (const float*)d_in[17];
    const float* mlp_b2 = (const float*)d_in[18];
    float* out = (float*)d_out;

    float *p_sum, *p_sumsq, *p_h, *p_mult, *p_qkv, *p_oatt, *p_x2, *p_m1;
    cudaGetSymbolAddress((void**)&p_sum,   g_sum);
    cudaGetSymbolAddress((void**)&p_sumsq, g_sumsq);
    cudaGetSymbolAddress((void**)&p_h,     g_h);
    cudaGetSymbolAddress((void**)&p_mult,  g_mult);
    cudaGetSymbolAddress((void**)&p_qkv,   g_qkv);
    cudaGetSymbolAddress((void**)&p_oatt,  g_oatt);
    cudaGetSymbolAddress((void**)&p_x2,    g_x2);
    cudaGetSymbolAddress((void**)&p_m1,    g_m1);

    // ---- norm 1 ----
    chan_stats_kernel<<<CC, 256>>>(x, p_sum, p_sumsq);
    ada_hidden_kernel<<<HID / 8, 256>>>(p_sum, n1_w1, n1_b1, p_h);
    ada_mult_kernel<<<CC / 8, 256>>>(p_h, n1_w2, n1_b2, scale1, p_sumsq, p_mult);

    // ---- qkv = (x * mult1)^T @ qkv_w^T + qkv_b : (4096, 576) ----
    gemm_kernel<1, 0><<<dim3(QKV3 / TN, NN / TM), 256>>>(
        NN, QKV3, CC,
        x, NN, p_mult,
        qkv_w, CC, nullptr,
        p_qkv, QKV3, qkv_b, /*bias_per_j=*/1, nullptr, 0);

    // ---- neighborhood attention -> oatt (4096, 192) ----
    natt_kernel<<<NN, NH * 32>>>(p_qkv, p_oatt);

    // ---- x2[c][n] = x[c][n] + proj_w @ oatt^T + proj_b ----
    gemm_kernel<0, 0><<<dim3(NN / TN, CC / TM), 256>>>(
        CC, NN, CC,
        proj_w, CC, nullptr,
        p_oatt, CC, nullptr,
        p_x2, NN, proj_b, /*bias_per_j=*/0, x, 0);

    // ---- norm 2 ----
    chan_stats_kernel<<<CC, 256>>>(p_x2, p_sum, p_sumsq);
    ada_hidden_kernel<<<HID / 8, 256>>>(p_sum, n2_w1, n2_b1, p_h);
    ada_mult_kernel<<<CC / 8, 256>>>(p_h, n2_w2, n2_b2, scale2, p_sumsq, p_mult);

    // ---- m1 = gelu(mlp_w1 @ (x2 * mult2) + b1) : (768, 4096) ----
    gemm_kernel<0, 1><<<dim3(NN / TN, MLPH / TM), 256>>>(
        MLPH, NN, CC,
        mlp_w1, CC, nullptr,
        p_x2, NN, p_mult,
        p_m1, NN, mlp_b1, /*bias_per_j=*/0, nullptr, /*gelu=*/1);

    // ---- out = x2 + mlp_w2 @ m1 + b2 : (192, 4096) ----
    gemm_kernel<0, 1><<<dim3(NN / TN, CC / TM), 256>>>(
        CC, NN, MLPH,
        mlp_w2, MLPH, nullptr,
        p_m1, NN, nullptr,
        out, NN, mlp_b2, /*bias_per_j=*/0, p_x2, 0);
}

// round 2
// speedup vs baseline: 1.7368x; 1.7368x over previous
#include <cuda_runtime.h>
#include <cuda_bf16.h>
#include <math.h>

// Fixed problem shapes
#define CC   192
#define NN   4096           // 16^3
#define HID  384
#define MLPH 768
#define NH   6
#define HD   32
#define QKV3 576

// ---------------- scratch ----------------------------------------------------
__device__ float g_sum[CC];
__device__ float g_sumsq[CC];
__device__ float g_h[HID];
__device__ float g_mult[CC];
__device__ float g_xT[(size_t)NN * CC];      // x transposed (pos, chan)
__device__ float g_qkv[(size_t)NN * QKV3];   // (pos, 576)
__device__ float g_oatt[(size_t)NN * CC];    // (pos, chan)
__device__ float g_x2[(size_t)NN * CC];      // (pos, chan)
__device__ float g_m1[(size_t)NN * MLPH];    // (pos, 768)
__device__ float g_y[(size_t)NN * CC];       // (pos, chan)

// ---------------- helpers ----------------------------------------------------
__device__ __forceinline__ float warp_sum(float v) {
#pragma unroll
    for (int o = 16; o; o >>= 1) v += __shfl_xor_sync(0xffffffffu, v, o);
    return v;
}
__device__ __forceinline__ float warp_max(float v) {
#pragma unroll
    for (int o = 16; o; o >>= 1) v = fmaxf(v, __shfl_xor_sync(0xffffffffu, v, o));
    return v;
}

// ---------------- transpose (R,C) -> (C,R) -----------------------------------
__global__ void transpose_k(const float* __restrict__ in, float* __restrict__ out,
                            int R, int C) {
    __shared__ float t[32][33];
    int c0 = blockIdx.x * 32, r0 = blockIdx.y * 32;
    int tx = threadIdx.x, ty = threadIdx.y;  // 32 x 8
#pragma unroll
    for (int u = 0; u < 32; u += 8)
        t[ty + u][tx] = in[(size_t)(r0 + ty + u) * C + c0 + tx];
    __syncthreads();
#pragma unroll
    for (int u = 0; u < 32; u += 8)
        out[(size_t)(c0 + ty + u) * R + r0 + tx] = t[tx][ty + u];
}

// ---------------- stats on x (chan, pos) row layout ---------------------------
__global__ void chan_stats_kernel(const float* __restrict__ x,
                                  float* __restrict__ sums,
                                  float* __restrict__ sumsq) {
    __shared__ float ss[8], ss2[8];
    int c = blockIdx.x;
    const float* p = x + (size_t)c * NN;
    float s = 0.f, s2 = 0.f;
    for (int i = threadIdx.x; i < NN; i += 256) {
        float v = p[i];
        s += v; s2 += v * v;
    }
    s = warp_sum(s); s2 = warp_sum(s2);
    int wid = threadIdx.x >> 5, lane = threadIdx.x & 31;
    if (lane == 0) { ss[wid] = s; ss2[wid] = s2; }
    __syncthreads();
    if (threadIdx.x == 0) {
        float a = 0.f, b = 0.f;
#pragma unroll
        for (int i = 0; i < 8; i++) { a += ss[i]; b += ss2[i]; }
        sums[c] = a; sumsq[c] = b;
    }
}

// ---------------- stats on (pos, chan) layout (column sums) ------------------
__global__ void col_stats_kernel(const float* __restrict__ xpc,
                                 float* __restrict__ sums,
                                 float* __restrict__ sumsq) {
    int c = threadIdx.x;             // 0..191
    int r0 = blockIdx.x * 64;
    float s = 0.f, s2 = 0.f;
    for (int r = r0; r < r0 + 64; r++) {
        float v = xpc[(size_t)r * CC + c];
        s += v; s2 += v * v;
    }
    atomicAdd(&sums[c], s);
    atomicAdd(&sumsq[c], s2);
}

// ---------------- ada gating MLP ----------------------------------------------
__global__ void ada_hidden_kernel(const float* __restrict__ sums,
                                  const float* __restrict__ w1,
                                  const float* __restrict__ b1,
                                  float* __restrict__ hout) {
    int gw = (blockIdx.x * blockDim.x + threadIdx.x) >> 5;
    int lane = threadIdx.x & 31;
    if (gw >= HID) return;
    const float* wr = w1 + (size_t)gw * CC;
    float acc = 0.f;
    for (int c = lane; c < CC; c += 32)
        acc += (sums[c] * (1.f / NN)) * wr[c];
    acc = warp_sum(acc);
    if (lane == 0) hout[gw] = fmaxf(acc + b1[gw], 0.f);
}

__global__ void ada_mult_kernel(const float* __restrict__ hvec,
                                const float* __restrict__ w2,
                                const float* __restrict__ b2,
                                const float* __restrict__ scale,
                                const float* __restrict__ sumsq,
                                float* __restrict__ mult) {
    int gw = (blockIdx.x * blockDim.x + threadIdx.x) >> 5;
    int lane = threadIdx.x & 31;
    if (gw >= CC) return;
    const float* wr = w2 + (size_t)gw * HID;
    float acc = 0.f;
    for (int i = lane; i < HID; i += 32) acc += hvec[i] * wr[i];
    acc = warp_sum(acc);
    if (lane == 0) {
        float g = 1.f / (1.f + __expf(-(acc + b2[gw])));
        mult[gw] = scale[gw] * g * rsqrtf(sumsq[gw] * (1.f / NN) + 1e-6f);
    }
}

// ---------------- SGEMM: out(M,N) = A(M,K)*diag?(Amult) @ B(N,K)^T -------------
// A row-major (M,K), B row-major (N,K). bias per output column j.
// Residual (M,N) added after optional GELU. M%128==0, N%64==0, K%16==0.
#define BM 128
#define BN 64
#define BK 16

template <int GELU, int RES>
__global__ void __launch_bounds__(256) gemm2(
    int M, int N, int K,
    const float* __restrict__ A, const float* __restrict__ Amult,
    const float* __restrict__ B,
    const float* __restrict__ bias,
    const float* __restrict__ residual,
    float* __restrict__ out) {
    __shared__ float As[2][BK][BM + 4];
    __shared__ float Bs[2][BK][BN + 4];
    const int i0 = blockIdx.y * BM;
    const int j0 = blockIdx.x * BN;
    const int tid = threadIdx.x;
    const int rl = tid >> 2;           // 0..63
    const int fl = (tid & 3) * 4;      // 0,4,8,12

    const float* Ap = A + (size_t)(i0 + rl) * K + fl;
    const float* Aq = A + (size_t)(i0 + rl + 64) * K + fl;
    const float* Bp = B + (size_t)(j0 + rl) * K + fl;

    float4 a0 = *(const float4*)Ap;
    float4 a1 = *(const float4*)Aq;
    float4 b0 = *(const float4*)Bp;
    float4 mm = Amult ? *(const float4*)(Amult + fl) : make_float4(1.f, 1.f, 1.f, 1.f);

    As[0][fl + 0][rl] = a0.x * mm.x;
    As[0][fl + 1][rl] = a0.y * mm.y;
    As[0][fl + 2][rl] = a0.z * mm.z;
    As[0][fl + 3][rl] = a0.w * mm.w;
    As[0][fl + 0][rl + 64] = a1.x * mm.x;
    As[0][fl + 1][rl + 64] = a1.y * mm.y;
    As[0][fl + 2][rl + 64] = a1.z * mm.z;
    As[0][fl + 3][rl + 64] = a1.w * mm.w;
    Bs[0][fl + 0][rl] = b0.x;
    Bs[0][fl + 1][rl] = b0.y;
    Bs[0][fl + 2][rl] = b0.z;
    Bs[0][fl + 3][rl] = b0.w;
    __syncthreads();

    float acc[8][4] = {};
    const int tx = tid & 15, ty = tid >> 4;
    const int nk = K / BK;

    for (int t = 0; t < nk; t++) {
        const int buf = t & 1;
        float4 na0, na1, nb0, nmm;
        if (t + 1 < nk) {
            int off = (t + 1) * BK;
            na0 = *(const float4*)(Ap + off);
            na1 = *(const float4*)(Aq + off);
            nb0 = *(const float4*)(Bp + off);
            nmm = Amult ? *(const float4*)(Amult + off + fl) : make_float4(1.f, 1.f, 1.f, 1.f);
        }
#pragma unroll
        for (int kk = 0; kk < BK; kk++) {
            float4 x0 = *(const float4*)&As[buf][kk][ty * 8];
            float4 x1 = *(const float4*)&As[buf][kk][ty * 8 + 4];
            float4 y0 = *(const float4*)&Bs[buf][kk][tx * 4];
            float av[8] = {x0.x, x0.y, x0.z, x0.w, x1.x, x1.y, x1.z, x1.w};
            float bv[4] = {y0.x, y0.y, y0.z, y0.w};
#pragma unroll
            for (int u = 0; u < 8; u++)
#pragma unroll
                for (int v = 0; v < 4; v++)
                    acc[u][v] = fmaf(av[u], bv[v], acc[u][v]);
        }
        if (t + 1 < nk) {
            const int nb = buf ^ 1;
            As[nb][fl + 0][rl] = na0.x * nmm.x;
            As[nb][fl + 1][rl] = na0.y * nmm.y;
            As[nb][fl + 2][rl] = na0.z * nmm.z;
            As[nb][fl + 3][rl] = na0.w * nmm.w;
            As[nb][fl + 0][rl + 64] = na1.x * nmm.x;
            As[nb][fl + 1][rl + 64] = na1.y * nmm.y;
            As[nb][fl + 2][rl + 64] = na1.z * nmm.z;
            As[nb][fl + 3][rl + 64] = na1.w * nmm.w;
            Bs[nb][fl + 0][rl] = nb0.x;
            Bs[nb][fl + 1][rl] = nb0.y;
            Bs[nb][fl + 2][rl] = nb0.z;
            Bs[nb][fl + 3][rl] = nb0.w;
            __syncthreads();
        }
    }

    float4 bs4 = *(const float4*)(bias + j0 + tx * 4);
    float bb[4] = {bs4.x, bs4.y, bs4.z, bs4.w};
#pragma unroll
    for (int u = 0; u < 8; u++) {
        int i = i0 + ty * 8 + u;
        float vals[4];
#pragma unroll
        for (int v = 0; v < 4; v++) {
            float val = acc[u][v] + bb[v];
            if (GELU) val = 0.5f * val * (1.f + erff(val * 0.70710678118654752f));
            vals[v] = val;
        }
        if (RES) {
            float4 r4 = *(const float4*)(residual + (size_t)i * N + j0 + tx * 4);
            vals[0] += r4.x; vals[1] += r4.y; vals[2] += r4.z; vals[3] += r4.w;
        }
        *(float4*)(out + (size_t)i * N + j0 + tx * 4) =
            make_float4(vals[0], vals[1], vals[2], vals[3]);
    }
}

// ---------------- tiled neighborhood attention --------------------------------
// CTA = (4x4x4 position block, head). Stage 8x8x8 k/v neighborhood in smem.
struct NattSmem {
    float qs[64 * 32];     // q rows, broadcast reads
    float ks[512 * 34];    // pad 34 -> conflict-free
    float vs[512 * 34];
    float4 pr[8 * 64];     // per-warp 128 (p, row) float2 pairs
};

extern __shared__ char natt_raw[];

__global__ void natt_tiled(const float* __restrict__ qkv, float* __restrict__ oatt) {
    NattSmem* S = (NattSmem*)natt_raw;
    const int bx = blockIdx.x;
    const int hy = blockIdx.y;
    const int bd = bx >> 4, bh = (bx >> 2) & 3, bw = bx & 3;
    const int base_d = min(max(4 * bd - 2, 0), 8);
    const int base_h = min(max(4 * bh - 2, 0), 8);
    const int base_w = min(max(4 * bw - 2, 0), 8);
    const int tid = threadIdx.x;

    // load q for 64 positions
    for (int idx = tid; idx < 64 * 8; idx += 256) {
        int p = idx >> 3, c4 = idx & 7;
        int n = (4 * bd + (p >> 4)) * 256 + (4 * bh + ((p >> 2) & 3)) * 16 + (4 * bw + (p & 3));
        float4 v = *(const float4*)(qkv + (size_t)n * QKV3 + hy * 32 + c4 * 4);
        float* dst = &S->qs[p * 32 + c4 * 4];
        dst[0] = v.x; dst[1] = v.y; dst[2] = v.z; dst[3] = v.w;
    }
    // load k, v for 512 neighborhood rows
    for (int idx = tid; idx < 512 * 8; idx += 256) {
        int r = idx >> 3, c4 = idx & 7;
        int n = (base_d + (r >> 6)) * 256 + (base_h + ((r >> 3) & 7)) * 16 + (base_w + (r & 7));
        const float* src = qkv + (size_t)n * QKV3 + CC + hy * 32 + c4 * 4;
        float4 kv = *(const float4*)src;
        float4 vv = *(const float4*)(src + CC);
        float* kd = &S->ks[r * 34 + c4 * 4];
        kd[0] = kv.x; kd[1] = kv.y; kd[2] = kv.z; kd[3] = kv.w;
        float* vd = &S->vs[r * 34 + c4 * 4];
        vd[0] = vv.x; vd[1] = vv.y; vd[2] = vv.z; vd[3] = vv.w;
    }
    __syncthreads();

    const int w_ = tid >> 5, l = tid & 31;
    float2* prw = (float2*)&S->pr[w_ * 64];
    const float scaleqk = 0.17677669529663689f;  // 1/sqrt(32)

    for (int i = 0; i < 8; i++) {
        int p = w_ * 8 + i;
        int d = 4 * bd + (p >> 4), h = 4 * bh + ((p >> 2) & 3), w = 4 * bw + (p & 3);
        int ld0 = min(max(d - 2, 0), 11) - base_d;
        int lh0 = min(max(h - 2, 0), 11) - base_h;
        int lw0 = min(max(w - 2, 0), 11) - base_w;

        int r[4];
        float s[4];
#pragma unroll
        for (int jj = 0; jj < 4; jj++) {
            int j = l + 32 * jj;
            int jd, jh, jw;
            if (j < 125) { jd = j / 25; jh = (j / 5) % 5; jw = j % 5; }
            else { jd = jh = jw = 0; }
            r[jj] = ((ld0 + jd) * 8 + (lh0 + jh)) * 8 + (lw0 + jw);
            s[jj] = 0.f;
        }
        const float* qrow = &S->qs[p * 32];
#pragma unroll
        for (int c2 = 0; c2 < 16; c2++) {
            float2 q2 = *(const float2*)(qrow + 2 * c2);
#pragma unroll
            for (int jj = 0; jj < 4; jj++) {
                float2 k2 = *(const float2*)(&S->ks[r[jj] * 34 + 2 * c2]);
                s[jj] = fmaf(q2.x, k2.x, fmaf(q2.y, k2.y, s[jj]));
            }
        }
#pragma unroll
        for (int jj = 0; jj < 4; jj++) s[jj] *= scaleqk;
        if (l >= 29) s[3] = -1e30f;

        float mx = fmaxf(fmaxf(s[0], s[1]), fmaxf(s[2], s[3]));
        mx = warp_max(mx);
        float e[4], tot = 0.f;
#pragma unroll
        for (int jj = 0; jj < 4; jj++) { e[jj] = __expf(s[jj] - mx); tot += e[jj]; }
        if (l >= 29) { e[3] = 0.f; tot -= __expf(s[3] - mx); }
        tot = warp_sum(tot);
        float inv = 1.f / tot;
#pragma unroll
        for (int jj = 0; jj < 4; jj++)
            prw[l + 32 * jj] = make_float2(e[jj], __int_as_float(r[jj]));
        __syncwarp();

        float acc = 0.f;
        const float4* pr4 = (const float4*)prw;
#pragma unroll 4
        for (int jb = 0; jb < 64; jb++) {
            float4 t0 = pr4[jb];
            acc = fmaf(t0.x, S->vs[__float_as_int(t0.y) * 34 + l], acc);
            acc = fmaf(t0.z, S->vs[__float_as_int(t0.w) * 34 + l], acc);
        }
        int n = d * 256 + h * 16 + w;
        oatt[(size_t)n * CC + hy * 32 + l] = acc * inv;
        __syncwarp();
    }
}

// ---------------- launch -------------------------------------------------------
extern "C" void kernel_launch(void* const* d_in, const int* in_sizes, int n_in,
                              void* d_out, int out_size) {
    const float* x      = (const float*)d_in[0];
    const float* scale1 = (const float*)d_in[1];
    const float* n1_w1  = (const float*)d_in[2];
    const float* n1_b1  = (const float*)d_in[3];
    const float* n1_w2  = (const float*)d_in[4];
    const float* n1_b2  = (const float*)d_in[5];
    const float* qkv_w  = (const float*)d_in[6];
    const float* qkv_b  = (const float*)d_in[7];
    const float* proj_w = (const float*)d_in[8];
    const float* proj_b = (const float*)d_in[9];
    const float* scale2 = (const float*)d_in[10];
    const float* n2_w1  = (const float*)d_in[11];
    const float* n2_b1  = (const float*)d_in[12];
    const float* n2_w2  = (const float*)d_in[13];
    const float* n2_b2  = (const float*)d_in[14];
    const float* mlp_w1 = (const float*)d_in[15];
    const float* mlp_b1 = (const float*)d_in[16];
    const float* mlp_w2 = (const float*)d_in[17];
    const float* mlp_b2 = (const float*)d_in[18];
    float* out = (float*)d_out;

    float *p_sum, *p_sumsq, *p_h, *p_mult, *p_xT, *p_qkv, *p_oatt, *p_x2, *p_m1, *p_y;
    cudaGetSymbolAddress((void**)&p_sum,   g_sum);
    cudaGetSymbolAddress((void**)&p_sumsq, g_sumsq);
    cudaGetSymbolAddress((void**)&p_h,     g_h);
    cudaGetSymbolAddress((void**)&p_mult,  g_mult);
    cudaGetSymbolAddress((void**)&p_xT,    g_xT);
    cudaGetSymbolAddress((void**)&p_qkv,   g_qkv);
    cudaGetSymbolAddress((void**)&p_oatt,  g_oatt);
    cudaGetSymbolAddress((void**)&p_x2,    g_x2);
    cudaGetSymbolAddress((void**)&p_m1,    g_m1);
    cudaGetSymbolAddress((void**)&p_y,     g_y);

    static bool attr_done = false;
    if (!attr_done) {
        cudaFuncSetAttribute(natt_tiled, cudaFuncAttributeMaxDynamicSharedMemorySize,
                             (int)sizeof(NattSmem));
        attr_done = true;
    }

    // ---- x^T (pos, chan) + stats for norm1 ----
    transpose_k<<<dim3(NN / 32, CC / 32), dim3(32, 8)>>>(x, p_xT, CC, NN);
    chan_stats_kernel<<<CC, 256>>>(x, p_sum, p_sumsq);
    ada_hidden_kernel<<<HID / 8, 256>>>(p_sum, n1_w1, n1_b1, p_h);
    ada_mult_kernel<<<CC / 8, 256>>>(p_h, n1_w2, n1_b2, scale1, p_sumsq, p_mult);

    // ---- qkv = (xT * mult1) @ qkv_w^T + b : (4096, 576) ----
    gemm2<0, 0><<<dim3(QKV3 / BN, NN / BM), 256>>>(
        NN, QKV3, CC, p_xT, p_mult, qkv_w, qkv_b, nullptr, p_qkv);

    // ---- neighborhood attention ----
    natt_tiled<<<dim3(64, NH), 256, sizeof(NattSmem)>>>(p_qkv, p_oatt);

    // ---- x2 = xT + oatt @ proj_w^T + b : (4096, 192) ----
    gemm2<0, 1><<<dim3(CC / BN, NN / BM), 256>>>(
        NN, CC, CC, p_oatt, nullptr, proj_w, proj_b, p_xT, p_x2);

    // ---- norm2 stats on (pos, chan) ----
    cudaMemsetAsync(p_sum, 0, CC * sizeof(float));
    cudaMemsetAsync(p_sumsq, 0, CC * sizeof(float));
    col_stats_kernel<<<64, CC>>>(p_x2, p_sum, p_sumsq);
    ada_hidden_kernel<<<HID / 8, 256>>>(p_sum, n2_w1, n2_b1, p_h);
    ada_mult_kernel<<<CC / 8, 256>>>(p_h, n2_w2, n2_b2, scale2, p_sumsq, p_mult);

    // ---- m1 = gelu((x2 * mult2) @ mlp_w1^T + b1) : (4096, 768) ----
    gemm2<1, 0><<<dim3(MLPH / BN, NN / BM), 256>>>(
        NN, MLPH, CC, p_x2, p_mult, mlp_w1, mlp_b1, nullptr, p_m1);

    // ---- y = x2 + m1 @ mlp_w2^T + b2 : (4096, 192) ----
    gemm2<0, 1><<<dim3(CC / BN, NN / BM), 256>>>(
        NN, CC, MLPH, p_m1, nullptr, mlp_w2, mlp_b2, p_x2, p_y);

    // ---- out = y^T : (192, 4096) ----
    transpose_k<<<dim3(CC / 32, NN / 32), dim3(32, 8)>>>(p_y, out, NN, CC);
}

// round 3
// speedup vs baseline: 2.0037x; 1.1537x over previous
#include <cuda_runtime.h>
#include <cuda_bf16.h>
#include <cstdint>
#include <math.h>

// Fixed problem shapes
#define CC   192
#define NN   4096           // 16^3
#define HID  384
#define MLPH 768
#define NH   6
#define HD   32
#define QKV3 576

// ---------------- scratch ----------------------------------------------------
__device__ float g_stats[2 * CC];            // [0:192)=sum, [192:384)=sumsq
__device__ float g_mult[CC];
__device__ float g_xT[(size_t)NN * CC];      // x transposed (pos, chan)
__device__ float g_qkv[(size_t)NN * QKV3];   // (pos, 576)
__device__ float g_oatt[(size_t)NN * CC];    // (pos, chan)
__device__ float g_x2[(size_t)NN * CC];      // (pos, chan)
__device__ float g_m1[(size_t)NN * MLPH];    // (pos, 768)
__device__ float g_y[(size_t)NN * CC];       // (pos, chan)

// ---------------- helpers ----------------------------------------------------
__device__ __forceinline__ float warp_sum(float v) {
#pragma unroll
    for (int o = 16; o; o >>= 1) v += __shfl_xor_sync(0xffffffffu, v, o);
    return v;
}
__device__ __forceinline__ float warp_max(float v) {
#pragma unroll
    for (int o = 16; o; o >>= 1) v = fmaxf(v, __shfl_xor_sync(0xffffffffu, v, o));
    return v;
}
__device__ __forceinline__ uint32_t f2tf(float x) {
    uint32_t r;
    asm("cvt.rna.tf32.f32 %0, %1;" : "=r"(r) : "f"(x));
    return r;
}
__device__ __forceinline__ void mma_tf32(float* c, const uint32_t* a, const uint32_t* b) {
    asm volatile(
        "mma.sync.aligned.m16n8k8.row.col.f32.tf32.tf32.f32 "
        "{%0,%1,%2,%3}, {%4,%5,%6,%7}, {%8,%9}, {%0,%1,%2,%3};\n"
        : "+f"(c[0]), "+f"(c[1]), "+f"(c[2]), "+f"(c[3])
        : "r"(a[0]), "r"(a[1]), "r"(a[2]), "r"(a[3]), "r"(b[0]), "r"(b[1]));
}

// ---------------- fused transpose (C,N)->(N,C) + per-channel stats ------------
__global__ void transpose_stats(const float* __restrict__ in, float* __restrict__ outp,
                                float* __restrict__ stats) {
    __shared__ float tle[32][33];
    int c0 = blockIdx.x * 32;  // position block
    int r0 = blockIdx.y * 32;  // channel block
    int tx = threadIdx.x, ty = threadIdx.y;
#pragma unroll
    for (int u = 0; u < 32; u += 8)
        tle[ty + u][tx] = in[(size_t)(r0 + ty + u) * NN + c0 + tx];
    __syncthreads();
#pragma unroll
    for (int u = 0; u < 32; u += 8)
        outp[(size_t)(c0 + ty + u) * CC + r0 + tx] = tle[tx][ty + u];
    if (ty == 0) {
        float s = 0.f, s2 = 0.f;
#pragma unroll
        for (int p = 0; p < 32; p++) { float v = tle[tx][p]; s += v; s2 += v * v; }
        atomicAdd(&stats[r0 + tx], s);
        atomicAdd(&stats[CC + r0 + tx], s2);
    }
}

// ---------------- plain transpose (R,C) -> (C,R) ------------------------------
__global__ void transpose_k(const float* __restrict__ in, float* __restrict__ out,
                            int R, int C) {
    __shared__ float t[32][33];
    int c0 = blockIdx.x * 32, r0 = blockIdx.y * 32;
    int tx = threadIdx.x, ty = threadIdx.y;
#pragma unroll
    for (int u = 0; u < 32; u += 8)
        t[ty + u][tx] = in[(size_t)(r0 + ty + u) * C + c0 + tx];
    __syncthreads();
#pragma unroll
    for (int u = 0; u < 32; u += 8)
        out[(size_t)(c0 + ty + u) * R + r0 + tx] = t[tx][ty + u];
}

// ---------------- fused ada gating (hidden + mult + optional zero) ------------
__global__ void __launch_bounds__(512) ada_fused(
    float* __restrict__ stats,
    const float* __restrict__ w1, const float* __restrict__ b1,
    const float* __restrict__ w2, const float* __restrict__ b2,
    const float* __restrict__ scale, float* __restrict__ mult, int zero) {
    __shared__ float mean_s[CC];
    __shared__ float h_s[HID];
    int tid = threadIdx.x, wid = tid >> 5, lane = tid & 31;
    if (tid < CC) mean_s[tid] = stats[tid] * (1.f / NN);
    __syncthreads();
    for (int r = wid; r < HID; r += 16) {
        const float* wr = w1 + (size_t)r * CC;
        float a = 0.f;
#pragma unroll
        for (int c = lane; c < CC; c += 32) a += mean_s[c] * wr[c];
        a = warp_sum(a);
        if (lane == 0) h_s[r] = fmaxf(a + b1[r], 0.f);
    }
    __syncthreads();
    for (int r = wid; r < CC; r += 16) {
        const float* wr = w2 + (size_t)r * HID;
        float a = 0.f;
#pragma unroll
        for (int i = lane; i < HID; i += 32) a += h_s[i] * wr[i];
        a = warp_sum(a);
        if (lane == 0) {
            float g = 1.f / (1.f + __expf(-(a + b2[r])));
            mult[r] = scale[r] * g * rsqrtf(stats[CC + r] * (1.f / NN) + 1e-6f);
        }
    }
    if (zero) {
        __syncthreads();
        if (tid < 2 * CC) stats[tid] = 0.f;
    }
}

// ---------------- tf32 tensor-core GEMM ---------------------------------------
// out(M,N) = epi( A(M,K)*diag(Amult) @ B(N,K)^T + bias[col] )  [+residual] [stats]
// CTA tile 128x64x16, 8 warps of 32x32, mma.m16n8k8.tf32.
#define SA 20   // smem row stride (16 + 4 pad) -> conflict-free fragment loads

template <int GELU, int RES, int STATS>
__global__ void __launch_bounds__(256) gemm_tc(
    int M, int N, int K,
    const float* __restrict__ A, const float* __restrict__ Amult,
    const float* __restrict__ B,
    const float* __restrict__ bias,
    const float* __restrict__ residual,
    float* __restrict__ out,
    float* __restrict__ stats) {
    __shared__ uint32_t As[2][128 * SA];
    __shared__ uint32_t Bs[2][64 * SA];

    const int i0 = blockIdx.y * 128, j0 = blockIdx.x * 64;
    const int tid = threadIdx.x;
    const int rl = tid >> 2, fl = (tid & 3) * 4;
    const int warp = tid >> 5, lane = tid & 31;
    const int wm = warp >> 1, wn = warp & 1;
    const int gid = lane >> 2, tig = lane & 3;

    const float* Ap = A + (size_t)(i0 + rl) * K + fl;
    const float* Aq = A + (size_t)(i0 + rl + 64) * K + fl;
    const float* Bp = B + (size_t)(j0 + rl) * K + fl;

    // preload tile 0
    {
        float4 a0 = *(const float4*)Ap;
        float4 a1 = *(const float4*)Aq;
        float4 b0 = *(const float4*)Bp;
        float4 mm = Amult ? *(const float4*)(Amult + fl) : make_float4(1.f, 1.f, 1.f, 1.f);
        uint4 ua = make_uint4(f2tf(a0.x * mm.x), f2tf(a0.y * mm.y),
                              f2tf(a0.z * mm.z), f2tf(a0.w * mm.w));
        uint4 ub = make_uint4(f2tf(a1.x * mm.x), f2tf(a1.y * mm.y),
                              f2tf(a1.z * mm.z), f2tf(a1.w * mm.w));
        uint4 uc = make_uint4(f2tf(b0.x), f2tf(b0.y), f2tf(b0.z), f2tf(b0.w));
        *(uint4*)&As[0][rl * SA + fl] = ua;
        *(uint4*)&As[0][(rl + 64) * SA + fl] = ub;
        *(uint4*)&Bs[0][rl * SA + fl] = uc;
    }
    __syncthreads();

    float acc[2][4][4] = {};
    const int nk = K / 16;

    for (int t = 0; t < nk; t++) {
        const int buf = t & 1;
        float4 na0, na1, nb0, nmm;
        if (t + 1 < nk) {
            int off = (t + 1) * 16;
            na0 = *(const float4*)(Ap + off);
            na1 = *(const float4*)(Aq + off);
            nb0 = *(const float4*)(Bp + off);
            nmm = Amult ? *(const float4*)(Amult + off + fl) : make_float4(1.f, 1.f, 1.f, 1.f);
        }
#pragma unroll
        for (int kc = 0; kc < 16; kc += 8) {
            uint32_t af[2][4], bf[4][2];
#pragma unroll
            for (int mt = 0; mt < 2; mt++) {
                int r0 = (wm * 32 + mt * 16 + gid) * SA + kc + tig;
                af[mt][0] = As[buf][r0];
                af[mt][1] = As[buf][r0 + 8 * SA];
                af[mt][2] = As[buf][r0 + 4];
                af[mt][3] = As[buf][r0 + 8 * SA + 4];
            }
#pragma unroll
            for (int nt = 0; nt < 4; nt++) {
                int n0 = (wn * 32 + nt * 8 + gid) * SA + kc + tig;
                bf[nt][0] = Bs[buf][n0];
                bf[nt][1] = Bs[buf][n0 + 4];
            }
#pragma unroll
            for (int mt = 0; mt < 2; mt++)
#pragma unroll
                for (int nt = 0; nt < 4; nt++)
                    mma_tf32(acc[mt][nt], af[mt], bf[nt]);
        }
        if (t + 1 < nk) {
            const int nb = buf ^ 1;
            uint4 ua = make_uint4(f2tf(na0.x * nmm.x), f2tf(na0.y * nmm.y),
                                  f2tf(na0.z * nmm.z), f2tf(na0.w * nmm.w));
            uint4 ub = make_uint4(f2tf(na1.x * nmm.x), f2tf(na1.y * nmm.y),
                                  f2tf(na1.z * nmm.z), f2tf(na1.w * nmm.w));
            uint4 uc = make_uint4(f2tf(nb0.x), f2tf(nb0.y), f2tf(nb0.z), f2tf(nb0.w));
            *(uint4*)&As[nb][rl * SA + fl] = ua;
            *(uint4*)&As[nb][(rl + 64) * SA + fl] = ub;
            *(uint4*)&Bs[nb][rl * SA + fl] = uc;
            __syncthreads();
        }
    }

    // epilogue
    float s0[4] = {}, s1[4] = {}, q0[4] = {}, q1[4] = {};
#pragma unroll
    for (int mt = 0; mt < 2; mt++) {
        int row = i0 + wm * 32 + mt * 16 + gid;
#pragma unroll
        for (int nt = 0; nt < 4; nt++) {
            int col = j0 + wn * 32 + nt * 8 + tig * 2;
            float bia0 = bias[col], bia1 = bias[col + 1];
            float v0 = acc[mt][nt][0] + bia0, v1 = acc[mt][nt][1] + bia1;
            float v2 = acc[mt][nt][2] + bia0, v3 = acc[mt][nt][3] + bia1;
            if (GELU) {
                v0 = 0.5f * v0 * (1.f + erff(v0 * 0.70710678118654752f));
                v1 = 0.5f * v1 * (1.f + erff(v1 * 0.70710678118654752f));
                v2 = 0.5f * v2 * (1.f + erff(v2 * 0.70710678118654752f));
                v3 = 0.5f * v3 * (1.f + erff(v3 * 0.70710678118654752f));
            }
            if (RES) {
                float2 r0 = *(const float2*)(residual + (size_t)row * N + col);
                float2 r1 = *(const float2*)(residual + (size_t)(row + 8) * N + col);
                v0 += r0.x; v1 += r0.y; v2 += r1.x; v3 += r1.y;
            }
            *(float2*)(out + (size_t)row * N + col) = make_float2(v0, v1);
            *(float2*)(out + (size_t)(row + 8) * N + col) = make_float2(v2, v3);
            if (STATS) {
                s0[nt] += v0 + v2; s1[nt] += v1 + v3;
                q0[nt] += v0 * v0 + v2 * v2; q1[nt] += v1 * v1 + v3 * v3;
            }
        }
    }
    if (STATS) {
#pragma unroll
        for (int nt = 0; nt < 4; nt++) {
#pragma unroll
            for (int o = 4; o < 32; o <<= 1) {
                s0[nt] += __shfl_xor_sync(0xffffffffu, s0[nt], o);
                s1[nt] += __shfl_xor_sync(0xffffffffu, s1[nt], o);
                q0[nt] += __shfl_xor_sync(0xffffffffu, q0[nt], o);
                q1[nt] += __shfl_xor_sync(0xffffffffu, q1[nt], o);
            }
            if (gid == 0) {
                int col = j0 + wn * 32 + nt * 8 + tig * 2;
                atomicAdd(&stats[col], s0[nt]);
                atomicAdd(&stats[col + 1], s1[nt]);
                atomicAdd(&stats[CC + col], q0[nt]);
                atomicAdd(&stats[CC + col + 1], q1[nt]);
            }
        }
    }
}

// ---------------- tiled neighborhood attention --------------------------------
struct NattSmem {
    float qs[64 * 32];
    float ks[512 * 34];
    float vs[512 * 34];
    float4 pr[8 * 64];
};
extern __shared__ char natt_raw[];

__global__ void natt_tiled(const float* __restrict__ qkv, float* __restrict__ oatt) {
    NattSmem* S = (NattSmem*)natt_raw;
    const int bx = blockIdx.x;
    const int hy = blockIdx.y;
    const int bd = bx >> 4, bh = (bx >> 2) & 3, bw = bx & 3;
    const int base_d = min(max(4 * bd - 2, 0), 8);
    const int base_h = min(max(4 * bh - 2, 0), 8);
    const int base_w = min(max(4 * bw - 2, 0), 8);
    const int tid = threadIdx.x;

    for (int idx = tid; idx < 64 * 8; idx += 256) {
        int p = idx >> 3, c4 = idx & 7;
        int n = (4 * bd + (p >> 4)) * 256 + (4 * bh + ((p >> 2) & 3)) * 16 + (4 * bw + (p & 3));
        float4 v = *(const float4*)(qkv + (size_t)n * QKV3 + hy * 32 + c4 * 4);
        float* dst = &S->qs[p * 32 + c4 * 4];
        dst[0] = v.x; dst[1] = v.y; dst[2] = v.z; dst[3] = v.w;
    }
    for (int idx = tid; idx < 512 * 8; idx += 256) {
        int r = idx >> 3, c4 = idx & 7;
        int n = (base_d + (r >> 6)) * 256 + (base_h + ((r >> 3) & 7)) * 16 + (base_w + (r & 7));
        const float* src = qkv + (size_t)n * QKV3 + CC + hy * 32 + c4 * 4;
        float4 kv = *(const float4*)src;
        float4 vv = *(const float4*)(src + CC);
        float* kd = &S->ks[r * 34 + c4 * 4];
        kd[0] = kv.x; kd[1] = kv.y; kd[2] = kv.z; kd[3] = kv.w;
        float* vd = &S->vs[r * 34 + c4 * 4];
        vd[0] = vv.x; vd[1] = vv.y; vd[2] = vv.z; vd[3] = vv.w;
    }
    __syncthreads();

    const int w_ = tid >> 5, l = tid & 31;
    float2* prw = (float2*)&S->pr[w_ * 64];
    const float scaleqk = 0.17677669529663689f;

    for (int i = 0; i < 8; i++) {
        int p = w_ * 8 + i;
        int d = 4 * bd + (p >> 4), h = 4 * bh + ((p >> 2) & 3), w = 4 * bw + (p & 3);
        int ld0 = min(max(d - 2, 0), 11) - base_d;
        int lh0 = min(max(h - 2, 0), 11) - base_h;
        int lw0 = min(max(w - 2, 0), 11) - base_w;

        int r[4];
        float s[4];
#pragma unroll
        for (int jj = 0; jj < 4; jj++) {
            int j = l + 32 * jj;
            int jd, jh, jw;
            if (j < 125) { jd = j / 25; jh = (j / 5) % 5; jw = j % 5; }
            else { jd = jh = jw = 0; }
            r[jj] = ((ld0 + jd) * 8 + (lh0 + jh)) * 8 + (lw0 + jw);
            s[jj] = 0.f;
        }
        const float* qrow = &S->qs[p * 32];
#pragma unroll
        for (int c2 = 0; c2 < 16; c2++) {
            float2 q2 = *(const float2*)(qrow + 2 * c2);
#pragma unroll
            for (int jj = 0; jj < 4; jj++) {
                float2 k2 = *(const float2*)(&S->ks[r[jj] * 34 + 2 * c2]);
                s[jj] = fmaf(q2.x, k2.x, fmaf(q2.y, k2.y, s[jj]));
            }
        }
#pragma unroll
        for (int jj = 0; jj < 4; jj++) s[jj] *= scaleqk;
        if (l >= 29) s[3] = -1e30f;

        float mx = fmaxf(fmaxf(s[0], s[1]), fmaxf(s[2], s[3]));
        mx = warp_max(mx);
        float e[4], tot = 0.f;
#pragma unroll
        for (int jj = 0; jj < 4; jj++) { e[jj] = __expf(s[jj] - mx); tot += e[jj]; }
        if (l >= 29) { e[3] = 0.f; tot -= __expf(s[3] - mx); }
        tot = warp_sum(tot);
        float inv = 1.f / tot;
#pragma unroll
        for (int jj = 0; jj < 4; jj++)
            prw[l + 32 * jj] = make_float2(e[jj], __int_as_float(r[jj]));
        __syncwarp();

        float acc = 0.f;
        const float4* pr4 = (const float4*)prw;
#pragma unroll 4
        for (int jb = 0; jb < 64; jb++) {
            float4 t0 = pr4[jb];
            acc = fmaf(t0.x, S->vs[__float_as_int(t0.y) * 34 + l], acc);
            acc = fmaf(t0.z, S->vs[__float_as_int(t0.w) * 34 + l], acc);
        }
        int n = d * 256 + h * 16 + w;
        oatt[(size_t)n * CC + hy * 32 + l] = acc * inv;
        __syncwarp();
    }
}

// ---------------- launch -------------------------------------------------------
extern "C" void kernel_launch(void* const* d_in, const int* in_sizes, int n_in,
                              void* d_out, int out_size) {
    const float* x      = (const float*)d_in[0];
    const float* scale1 = (const float*)d_in[1];
    const float* n1_w1  = (const float*)d_in[2];
    const float* n1_b1  = (const float*)d_in[3];
    const float* n1_w2  = (const float*)d_in[4];
    const float* n1_b2  = (const float*)d_in[5];
    const float* qkv_w  = (const float*)d_in[6];
    const float* qkv_b  = (const float*)d_in[7];
    const float* proj_w = (const float*)d_in[8];
    const float* proj_b = (const float*)d_in[9];
    const float* scale2 = (const float*)d_in[10];
    const float* n2_w1  = (const float*)d_in[11];
    const float* n2_b1  = (const float*)d_in[12];
    const float* n2_w2  = (const float*)d_in[13];
    const float* n2_b2  = (const float*)d_in[14];
    const float* mlp_w1 = (const float*)d_in[15];
    const float* mlp_b1 = (const float*)d_in[16];
    const float* mlp_w2 = (const float*)d_in[17];
    const float* mlp_b2 = (const float*)d_in[18];
    float* out = (float*)d_out;

    float *p_stats, *p_mult, *p_xT, *p_qkv, *p_oatt, *p_x2, *p_m1, *p_y;
    cudaGetSymbolAddress((void**)&p_stats, g_stats);
    cudaGetSymbolAddress((void**)&p_mult,  g_mult);
    cudaGetSymbolAddress((void**)&p_xT,    g_xT);
    cudaGetSymbolAddress((void**)&p_qkv,   g_qkv);
    cudaGetSymbolAddress((void**)&p_oatt,  g_oatt);
    cudaGetSymbolAddress((void**)&p_x2,    g_x2);
    cudaGetSymbolAddress((void**)&p_m1,    g_m1);
    cudaGetSymbolAddress((void**)&p_y,     g_y);

    static bool attr_done = false;
    if (!attr_done) {
        cudaFuncSetAttribute(natt_tiled, cudaFuncAttributeMaxDynamicSharedMemorySize,
                             (int)sizeof(NattSmem));
        attr_done = true;
    }

    // zero stats (used by transpose_stats atomics)
    cudaMemsetAsync(p_stats, 0, 2 * CC * sizeof(float));

    // ---- transpose + norm1 stats ----
    transpose_stats<<<dim3(NN / 32, CC / 32), dim3(32, 8)>>>(x, p_xT, p_stats);
    ada_fused<<<1, 512>>>(p_stats, n1_w1, n1_b1, n1_w2, n1_b2, scale1, p_mult, /*zero=*/1);

    // ---- qkv = (xT * mult1) @ qkv_w^T + b : (4096, 576) ----
    gemm_tc<0, 0, 0><<<dim3(QKV3 / 64, NN / 128), 256>>>(
        NN, QKV3, CC, p_xT, p_mult, qkv_w, qkv_b, nullptr, p_qkv, nullptr);

    // ---- neighborhood attention ----
    natt_tiled<<<dim3(64, NH), 256, sizeof(NattSmem)>>>(p_qkv, p_oatt);

    // ---- x2 = xT + oatt @ proj_w^T + b; fused norm2 stats ----
    gemm_tc<0, 1, 1><<<dim3(CC / 64, NN / 128), 256>>>(
        NN, CC, CC, p_oatt, nullptr, proj_w, proj_b, p_xT, p_x2, p_stats);

    ada_fused<<<1, 512>>>(p_stats, n2_w1, n2_b1, n2_w2, n2_b2, scale2, p_mult, /*zero=*/0);

    // ---- m1 = gelu((x2 * mult2) @ mlp_w1^T + b1) : (4096, 768) ----
    gemm_tc<1, 0, 0><<<dim3(MLPH / 64, NN / 128), 256>>>(
        NN, MLPH, CC, p_x2, p_mult, mlp_w1, mlp_b1, nullptr, p_m1, nullptr);

    // ---- y = x2 + m1 @ mlp_w2^T + b2 : (4096, 192) ----
    gemm_tc<0, 1, 0><<<dim3(CC / 64, NN / 128), 256>>>(
        NN, CC, MLPH, p_m1, nullptr, mlp_w2, mlp_b2, p_x2, p_y, nullptr);

    // ---- out = y^T : (192, 4096) ----
    transpose_k<<<dim3(CC / 32, NN / 32), dim3(32, 8)>>>(p_y, out, NN, CC);
}